// round 3
// baseline (speedup 1.0000x reference)
#include <cuda_runtime.h>
#include <float.h>

#define HH 4
#define BB 1024
#define LL 200
#define DQv 512
#define DFv 128
#define DD1 128
#define DD2 64

// Collapsed weights + precomputed fq (static device scratch — allowed)
__device__ float g_Wq[HH * DQv * DD2];   // [h][k][c]
__device__ float g_bq[HH * DD2];
__device__ float g_Wc[HH * DFv * 128];   // [h][k][c]  c<64: f-path, c>=64: v-path
__device__ float g_bc[HH * 128];
__device__ float g_fq[BB * HH * DD2];    // [b][h][c] silu(query@Wq_eff+bq_eff)

// ---------------- packed f32x2 helpers ----------------
__device__ __forceinline__ void ffma2(unsigned long long& d, unsigned long long a, unsigned long long b) {
    asm("fma.rn.f32x2 %0, %1, %2, %0;" : "+l"(d) : "l"(a), "l"(b));
}
__device__ __forceinline__ float2 unpk(unsigned long long v) {
    unsigned int lo, hi;
    asm("mov.b64 {%0, %1}, %2;" : "=r"(lo), "=r"(hi) : "l"(v));
    return make_float2(__uint_as_float(lo), __uint_as_float(hi));
}
__device__ __forceinline__ float silu_f(float x) {
    return x / (1.f + __expf(-x));
}

// ---------------- weight collapse kernels ----------------
__global__ void collapse_q_kernel(const float* __restrict__ Wq1, const float* __restrict__ bq1,
                                  const float* __restrict__ Wq2, const float* __restrict__ bq2) {
    int idx = blockIdx.x * 256 + threadIdx.x;      // < 4*512*64 = 131072
    int c = idx & 63;
    int k = (idx >> 6) & 511;
    int h = idx >> 15;
    const float* a  = Wq1 + (h * DQv + k) * DD1;
    const float* w2 = Wq2 + h * DD1 * DD2 + c;
    float acc = 0.f;
#pragma unroll 8
    for (int j = 0; j < DD1; ++j) acc += a[j] * w2[j * DD2];
    g_Wq[idx] = acc;
    if (k == 0) {
        float bb = bq2[h * DD2 + c];
        const float* b1p = bq1 + h * DD1;
#pragma unroll 8
        for (int j = 0; j < DD1; ++j) bb += b1p[j] * w2[j * DD2];
        g_bq[h * DD2 + c] = bb;
    }
}

__global__ void collapse_fv_kernel(const float* __restrict__ Wf1, const float* __restrict__ bf1,
                                   const float* __restrict__ Wf2, const float* __restrict__ bf2,
                                   const float* __restrict__ Wv1, const float* __restrict__ bv1,
                                   const float* __restrict__ Wv2, const float* __restrict__ bv2) {
    int idx = blockIdx.x * 256 + threadIdx.x;      // < 4*128*128 = 65536
    int c = idx & 127;
    int k = (idx >> 7) & 127;
    int h = idx >> 14;
    const float *W1, *W2, *B1, *B2;
    int cc;
    if (c < 64) { W1 = Wf1; W2 = Wf2; B1 = bf1; B2 = bf2; cc = c; }
    else        { W1 = Wv1; W2 = Wv2; B1 = bv1; B2 = bv2; cc = c - 64; }
    const float* a  = W1 + (h * DFv + k) * DD1;
    const float* w2 = W2 + h * DD1 * DD2 + cc;
    float acc = 0.f;
#pragma unroll 8
    for (int j = 0; j < DD1; ++j) acc += a[j] * w2[j * DD2];
    g_Wc[idx] = acc;
    if (k == 0) {
        float bb = B2[h * DD2 + cc];
        const float* b1p = B1 + h * DD1;
#pragma unroll 8
        for (int j = 0; j < DD1; ++j) bb += b1p[j] * w2[j * DD2];
        g_bc[h * 128 + c] = bb;
    }
}

// ---------------- fq kernel: g_fq = silu(query @ Wq_eff + bq_eff) ----------------
__global__ __launch_bounds__(256) void fq_kernel(const float* __restrict__ query) {
    __shared__ float qs[32 * 68];
    __shared__ float ws[64 * 64];
    const int tid = threadIdx.x;
    const int h  = blockIdx.x & 3;
    const int bg = blockIdx.x >> 2;
    const int bl = tid >> 3;
    const int cg = tid & 7;

    float acc[8];
#pragma unroll
    for (int j = 0; j < 8; ++j) acc[j] = 0.f;

    for (int kc = 0; kc < 8; ++kc) {
        __syncthreads();
#pragma unroll
        for (int it = 0; it < 8; ++it) {
            int idx = tid + it * 256;
            int bb = idx >> 6, kk = idx & 63;
            qs[bb * 68 + kk] = query[(bg * 32 + bb) * DQv + kc * 64 + kk];
        }
#pragma unroll
        for (int it = 0; it < 16; ++it) {
            int idx = tid + it * 256;
            int kk = idx >> 6, cc = idx & 63;
            ws[kk * 64 + cc] = g_Wq[(h * DQv + kc * 64 + kk) * DD2 + cc];
        }
        __syncthreads();
#pragma unroll 4
        for (int k = 0; k < 64; ++k) {
            float qv = qs[bl * 68 + k];
            float4 w01 = *reinterpret_cast<const float4*>(ws + k * 64 + cg * 8);
            float4 w23 = *reinterpret_cast<const float4*>(ws + k * 64 + cg * 8 + 4);
            acc[0] += qv * w01.x; acc[1] += qv * w01.y;
            acc[2] += qv * w01.z; acc[3] += qv * w01.w;
            acc[4] += qv * w23.x; acc[5] += qv * w23.y;
            acc[6] += qv * w23.z; acc[7] += qv * w23.w;
        }
    }
    int bglob = bg * 32 + bl;
#pragma unroll
    for (int j = 0; j < 8; ++j) {
        int c = cg * 8 + j;
        float z = acc[j] + g_bq[h * DD2 + c];
        g_fq[bglob * 256 + h * 64 + c] = silu_f(z);
    }
}

// ---------------- fused main kernel: one block per (b,h), 2 CTAs/SM ----------------
// warps 0-3: f-path (cols 0-63), rows rg*10..rg*10+9 per 40-row tile -> logits
// warps 4-7: v-path (cols 64-127), same rows -> online softmax accumulation
// smem (floats): W 16384 | factd 10240 (40x256 dup) | logits 208 | fq 64 | bc 128
//                | merge_o 256 | merge_p 256 | misc 32
#define SMEM_FLOATS (16384 + 10240 + 208 + 64 + 128 + 256 + 256 + 32)
#define SMEM_BYTES  (SMEM_FLOATS * 4)

__global__ __launch_bounds__(256, 2) void mha_main_kernel(
    const float* __restrict__ fact,
    const int* __restrict__ mask, const float* __restrict__ mm,
    const float* __restrict__ tau1, const float* __restrict__ tau2,
    float* __restrict__ out)
{
    extern __shared__ float sm[];
    float* W_s      = sm;                 // [128 k][128 c]
    float* factd    = W_s + 16384;        // [40][256] duplicated pairs
    float* logits_s = factd + 10240;      // [200] (+pad)
    float* fq_s     = logits_s + 208;     // [64]
    float* bc_s     = fq_s + 64;          // [128]
    float* merge_o  = bc_s + 128;         // [4][64]
    float* merge_p  = merge_o + 256;      // [4][64]
    float* misc     = merge_p + 256;      // [32]

    const int tid = threadIdx.x;
    const int b = blockIdx.x >> 2;
    const int h = blockIdx.x & 3;
    const int rg   = tid >> 5;            // warp id 0..7
    const int lane = tid & 31;
    const int rgv  = rg & 3;              // row group 0..3
    const bool is_f = (rg < 4);
    const int cbase = is_f ? 0 : 64;      // column base for this warp
    const int lane2 = lane * 2;

    // stage combined weights
    {
        const float4* gw = reinterpret_cast<const float4*>(g_Wc + h * 16384);
        float4* ws4 = reinterpret_cast<float4*>(W_s);
#pragma unroll
        for (int i = 0; i < 16; ++i) ws4[tid + 256 * i] = gw[tid + 256 * i];
    }
    if (tid < 128) bc_s[tid] = g_bc[h * 128 + tid];
    if (tid < 64)  fq_s[tid] = g_fq[b * 256 + h * 64 + tid];
    __syncthreads();

    const float t1a = tau1[h], t1b = tau1[4 + h];
    const float cb1 = tau2[h], cb2 = tau2[4 + h], cb3 = tau2[8 + h];

    const float bc0 = bc_s[cbase + lane2];
    const float bc1 = bc_s[cbase + lane2 + 1];
    float fqv0 = 0.f, fqv1 = 0.f;
    if (is_f) { fqv0 = fq_s[lane2]; fqv1 = fq_s[lane2 + 1]; }

    // online-softmax state (v-warps); lane owns 2 v-columns
    float m_run = -FLT_MAX, S_run = 0.f;
    float o0 = 0.f, o1 = 0.f, p0 = 0.f, p1 = 0.f;

    const float4* fact4 = reinterpret_cast<const float4*>(fact + (long)b * 200 * 128);

#pragma unroll 1
    for (int t = 0; t < 5; ++t) {
        const int tb = t * 40;
        __syncthreads();  // all warps done reading factd(t-1)
        // stage 40-row fact tile, duplicated pairs
#pragma unroll
        for (int it = 0; it < 5; ++it) {
            int idx = tid + it * 256;            // < 1280
            int row = idx >> 5, q = idx & 31;
            float4 f = fact4[(tb + row) * 32 + q];
            float* dst = factd + row * 256 + q * 8;
            *reinterpret_cast<float4*>(dst)     = make_float4(f.x, f.x, f.y, f.y);
            *reinterpret_cast<float4*>(dst + 4) = make_float4(f.z, f.z, f.w, f.w);
        }
        __syncthreads();

        // ---- mainloop: 10 rows x 64 cols per warp, 2 cols/lane ----
        const int lbase = rgv * 10;
        unsigned long long acc[10];
#pragma unroll
        for (int i = 0; i < 10; ++i) acc[i] = 0ull;

#pragma unroll 4
        for (int k4 = 0; k4 < 32; ++k4) {
            const float* wp = W_s + (k4 * 4) * 128 + cbase + lane2;
            unsigned long long w0 = *reinterpret_cast<const unsigned long long*>(wp);
            unsigned long long w1 = *reinterpret_cast<const unsigned long long*>(wp + 128);
            unsigned long long w2 = *reinterpret_cast<const unsigned long long*>(wp + 256);
            unsigned long long w3 = *reinterpret_cast<const unsigned long long*>(wp + 384);
#pragma unroll
            for (int i = 0; i < 10; ++i) {
                const float* fp = factd + (lbase + i) * 256 + k4 * 8;
                ulonglong2 fa = *reinterpret_cast<const ulonglong2*>(fp);      // {f0,f0},{f1,f1}
                ulonglong2 fb = *reinterpret_cast<const ulonglong2*>(fp + 4);  // {f2,f2},{f3,f3}
                ffma2(acc[i], fa.x, w0);
                ffma2(acc[i], fa.y, w1);
                ffma2(acc[i], fb.x, w2);
                ffma2(acc[i], fb.y, w3);
            }
        }

        if (is_f) {
            // f-warps: silu, dot with fq (64-col dot via full-warp reduce), logits
            float pdot[10];
#pragma unroll
            for (int i = 0; i < 10; ++i) {
                float2 a = unpk(acc[i]);
                float s0 = silu_f(a.x + bc0);
                float s1 = silu_f(a.y + bc1);
                pdot[i] = s0 * fqv0 + s1 * fqv1;
#pragma unroll
                for (int off = 16; off > 0; off >>= 1)
                    pdot[i] += __shfl_xor_sync(0xffffffffu, pdot[i], off);
            }
            if (lane < 10) {
                float d0 = pdot[0];
#pragma unroll
                for (int i = 1; i < 10; ++i)
                    if (lane == i) d0 = pdot[i];
                int l = tb + lbase + lane;
                float mk = (float)mask[b * 200 + l];
                float dd = d0 + (-1e9f) * (1.f - mk);    // mask BEFORE cosine mixing
                float bias = mm[b * 200 + l] / t1a + mm[204800 + b * 200 + l] / t1b;
                logits_s[l] = cb1 * dd + cb2 * bias + cb3 * dd * bias;
            }
        }
        __syncthreads();   // logits(t) visible to v-warps

        if (!is_f) {
            // v-warps: silu then online-softmax accumulate
#pragma unroll
            for (int i = 0; i < 10; ++i) {
                float2 a = unpk(acc[i]);
                float v0 = silu_f(a.x + bc0);
                float v1 = silu_f(a.y + bc1);
                float lg = logits_s[tb + lbase + i];
                float mn = fmaxf(m_run, lg);
                float sc = expf(m_run - mn);   // 0 when m_run = -FLT_MAX
                float e  = expf(lg - mn);
                S_run = S_run * sc + e;
                o0 = o0 * sc + e * v0;
                o1 = o1 * sc + e * v1;
                p0 += v0;
                p1 += v1;
                m_run = mn;
            }
        }
    }

    // ---- merge 4 v-warp groups ----
    if (!is_f) {
        merge_o[rgv * 64 + lane2]     = o0;
        merge_o[rgv * 64 + lane2 + 1] = o1;
        merge_p[rgv * 64 + lane2]     = p0;
        merge_p[rgv * 64 + lane2 + 1] = p1;
        if (lane == 0) { misc[rgv] = m_run; misc[8 + rgv] = S_run; }
    }
    __syncthreads();

    if (tid < 64) {
        float M = fmaxf(fmaxf(misc[0], misc[1]), fmaxf(misc[2], misc[3]));
        float e0 = expf(misc[0] - M), e1 = expf(misc[1] - M);
        float e2 = expf(misc[2] - M), e3 = expf(misc[3] - M);
        float S = misc[8] * e0 + misc[9] * e1 + misc[10] * e2 + misc[11] * e3;
        float o = merge_o[tid] * e0 + merge_o[64 + tid] * e1
                + merge_o[128 + tid] * e2 + merge_o[192 + tid] * e3;
        float p = merge_p[tid] + merge_p[64 + tid] + merge_p[128 + tid] + merge_p[192 + tid];
        out[b * 256 + h * 64 + tid] = o / S + 1e-7f * p;
    }
}

extern "C" void kernel_launch(void* const* d_in, const int* in_sizes, int n_in,
                              void* d_out, int out_size) {
    const float* query = (const float*)d_in[0];
    const float* fact  = (const float*)d_in[1];
    const int*   mask  = (const int*)  d_in[2];
    const float* mm    = (const float*)d_in[3];
    const float* Wq1   = (const float*)d_in[4];
    const float* bq1   = (const float*)d_in[5];
    const float* Wq2   = (const float*)d_in[6];
    const float* bq2   = (const float*)d_in[7];
    const float* Wf1   = (const float*)d_in[8];
    const float* bf1   = (const float*)d_in[9];
    const float* Wf2   = (const float*)d_in[10];
    const float* bf2   = (const float*)d_in[11];
    const float* Wv1   = (const float*)d_in[12];
    const float* bv1   = (const float*)d_in[13];
    const float* Wv2   = (const float*)d_in[14];
    const float* bv2   = (const float*)d_in[15];
    const float* tau1  = (const float*)d_in[16];
    const float* tau2  = (const float*)d_in[17];
    float* out = (float*)d_out;

    cudaFuncSetAttribute(mha_main_kernel, cudaFuncAttributeMaxDynamicSharedMemorySize, SMEM_BYTES);

    collapse_q_kernel<<<512, 256>>>(Wq1, bq1, Wq2, bq2);
    collapse_fv_kernel<<<256, 256>>>(Wf1, bf1, Wf2, bf2, Wv1, bv1, Wv2, bv2);
    fq_kernel<<<128, 256>>>(query);
    mha_main_kernel<<<BB * HH, 256, SMEM_BYTES>>>(fact, mask, mm, tau1, tau2, out);
}

// round 4
// speedup vs baseline: 1.4839x; 1.4839x over previous
#include <cuda_runtime.h>
#include <float.h>

#define HH 4
#define BB 1024
#define LL 200
#define DQv 512
#define DFv 128
#define DD1 128
#define DD2 64

// Collapsed weights + precomputed fq (static device scratch — allowed)
__device__ float g_Wq[HH * DQv * DD2];   // [h][k][c]
__device__ float g_bq[HH * DD2];
__device__ float g_Wc[HH * DFv * 128];   // [h][k][c]  c<64: f-path, c>=64: v-path
__device__ float g_bc[HH * 128];
__device__ float g_fq[BB * HH * DD2];    // [b][h][c] silu(query@Wq_eff+bq_eff)

// ---------------- packed f32x2 helpers ----------------
__device__ __forceinline__ void ffma2(unsigned long long& d, unsigned long long a, unsigned long long b) {
    asm("fma.rn.f32x2 %0, %1, %2, %0;" : "+l"(d) : "l"(a), "l"(b));
}
__device__ __forceinline__ unsigned long long dup2(float x) {
    unsigned long long r;
    unsigned int u = __float_as_uint(x);
    asm("mov.b64 %0, {%1, %1};" : "=l"(r) : "r"(u));
    return r;
}
__device__ __forceinline__ float2 unpk(unsigned long long v) {
    unsigned int lo, hi;
    asm("mov.b64 {%0, %1}, %2;" : "=r"(lo), "=r"(hi) : "l"(v));
    return make_float2(__uint_as_float(lo), __uint_as_float(hi));
}
__device__ __forceinline__ float silu_f(float x) {
    return x / (1.f + __expf(-x));
}

// ---------------- weight collapse kernels ----------------
__global__ void collapse_q_kernel(const float* __restrict__ Wq1, const float* __restrict__ bq1,
                                  const float* __restrict__ Wq2, const float* __restrict__ bq2) {
    int idx = blockIdx.x * 256 + threadIdx.x;      // < 4*512*64 = 131072
    int c = idx & 63;
    int k = (idx >> 6) & 511;
    int h = idx >> 15;
    const float* a  = Wq1 + (h * DQv + k) * DD1;
    const float* w2 = Wq2 + h * DD1 * DD2 + c;
    float acc = 0.f;
#pragma unroll 8
    for (int j = 0; j < DD1; ++j) acc += a[j] * w2[j * DD2];
    g_Wq[idx] = acc;
    if (k == 0) {
        float bb = bq2[h * DD2 + c];
        const float* b1p = bq1 + h * DD1;
#pragma unroll 8
        for (int j = 0; j < DD1; ++j) bb += b1p[j] * w2[j * DD2];
        g_bq[h * DD2 + c] = bb;
    }
}

__global__ void collapse_fv_kernel(const float* __restrict__ Wf1, const float* __restrict__ bf1,
                                   const float* __restrict__ Wf2, const float* __restrict__ bf2,
                                   const float* __restrict__ Wv1, const float* __restrict__ bv1,
                                   const float* __restrict__ Wv2, const float* __restrict__ bv2) {
    int idx = blockIdx.x * 256 + threadIdx.x;      // < 4*128*128 = 65536
    int c = idx & 127;
    int k = (idx >> 7) & 127;
    int h = idx >> 14;
    const float *W1, *W2, *B1, *B2;
    int cc;
    if (c < 64) { W1 = Wf1; W2 = Wf2; B1 = bf1; B2 = bf2; cc = c; }
    else        { W1 = Wv1; W2 = Wv2; B1 = bv1; B2 = bv2; cc = c - 64; }
    const float* a  = W1 + (h * DFv + k) * DD1;
    const float* w2 = W2 + h * DD1 * DD2 + cc;
    float acc = 0.f;
#pragma unroll 8
    for (int j = 0; j < DD1; ++j) acc += a[j] * w2[j * DD2];
    g_Wc[idx] = acc;
    if (k == 0) {
        float bb = B2[h * DD2 + cc];
        const float* b1p = B1 + h * DD1;
#pragma unroll 8
        for (int j = 0; j < DD1; ++j) bb += b1p[j] * w2[j * DD2];
        g_bc[h * 128 + c] = bb;
    }
}

// ---------------- fq kernel ----------------
__global__ __launch_bounds__(256) void fq_kernel(const float* __restrict__ query) {
    __shared__ float qs[32 * 68];
    __shared__ float ws[64 * 64];
    const int tid = threadIdx.x;
    const int h  = blockIdx.x & 3;
    const int bg = blockIdx.x >> 2;
    const int bl = tid >> 3;
    const int cg = tid & 7;

    float acc[8];
#pragma unroll
    for (int j = 0; j < 8; ++j) acc[j] = 0.f;

    for (int kc = 0; kc < 8; ++kc) {
        __syncthreads();
#pragma unroll
        for (int it = 0; it < 8; ++it) {
            int idx = tid + it * 256;
            int bb = idx >> 6, kk = idx & 63;
            qs[bb * 68 + kk] = query[(bg * 32 + bb) * DQv + kc * 64 + kk];
        }
#pragma unroll
        for (int it = 0; it < 16; ++it) {
            int idx = tid + it * 256;
            int kk = idx >> 6, cc = idx & 63;
            ws[kk * 64 + cc] = g_Wq[(h * DQv + kc * 64 + kk) * DD2 + cc];
        }
        __syncthreads();
#pragma unroll 4
        for (int k = 0; k < 64; ++k) {
            float qv = qs[bl * 68 + k];
            float4 w01 = *reinterpret_cast<const float4*>(ws + k * 64 + cg * 8);
            float4 w23 = *reinterpret_cast<const float4*>(ws + k * 64 + cg * 8 + 4);
            acc[0] += qv * w01.x; acc[1] += qv * w01.y;
            acc[2] += qv * w01.z; acc[3] += qv * w01.w;
            acc[4] += qv * w23.x; acc[5] += qv * w23.y;
            acc[6] += qv * w23.z; acc[7] += qv * w23.w;
        }
    }
    int bglob = bg * 32 + bl;
#pragma unroll
    for (int j = 0; j < 8; ++j) {
        int c = cg * 8 + j;
        float z = acc[j] + g_bq[h * DD2 + c];
        g_fq[bglob * 256 + h * 64 + c] = silu_f(z);
    }
}

// ---------------- fused main kernel: one block per (b,h), 2 CTAs/SM ----------------
// 8 warps = 2 rb (20 rows each) x 4 cb (32 cols each). Lane: rg = lane>>4 (10 rows,
// 5 row-pairs), cg = lane&15 (2 cols). Row-pair-packed f32x2 accumulation:
// acc[p][c] = { out[2p][c], out[2p+1][c] }, multiplier pair loaded directly from
// transposed fact tile fdT[k][12*gg + j] (gg = 2rb+rg, j=0..9, pad to 12).
//
// smem floats: W 16384 | fdT 6144 | lg 48 | pd0 48 | pd1 48 | fq 64 | bc 128
//              | mo 256 | mp 256 | mS 16   -> 23392 floats = 93568 B -> 2 CTAs/SM
#define OFF_FDT  16384
#define OFF_LG   (OFF_FDT + 6144)
#define OFF_PD0  (OFF_LG + 48)
#define OFF_PD1  (OFF_PD0 + 48)
#define OFF_FQ   (OFF_PD1 + 48)
#define OFF_BC   (OFF_FQ + 64)
#define OFF_MO   (OFF_BC + 128)
#define OFF_MP   (OFF_MO + 256)
#define OFF_MS   (OFF_MP + 256)
#define SMEM_FLOATS (OFF_MS + 16)
#define SMEM_BYTES  (SMEM_FLOATS * 4)

__global__ __launch_bounds__(256, 2) void mha_main_kernel(
    const float* __restrict__ fact,
    const int* __restrict__ mask, const float* __restrict__ mm,
    const float* __restrict__ tau1, const float* __restrict__ tau2,
    float* __restrict__ out)
{
    extern __shared__ float sm[];
    float* W_s  = sm;              // [128 k][128 c]
    float* fdT  = sm + OFF_FDT;    // [128 k][48]  (4 gg-groups of 12: rows j=0..9 + pad)
    float* lg_s = sm + OFF_LG;     // [40]
    float* pd0  = sm + OFF_PD0;    // [40]
    float* pd1  = sm + OFF_PD1;    // [40]
    float* fq_s = sm + OFF_FQ;     // [64]
    float* bc_s = sm + OFF_BC;     // [128]
    float* mo   = sm + OFF_MO;     // [4][64]
    float* mp   = sm + OFF_MP;     // [4][64]
    float* mSs  = sm + OFF_MS;     // [8]

    const int tid = threadIdx.x;
    const int b = blockIdx.x >> 2;
    const int h = blockIdx.x & 3;
    const int w    = tid >> 5;
    const int lane = tid & 31;
    const int rb = w >> 2;             // 0,1
    const int cb = w & 3;              // 0..3 (0,1 = f cols; 2,3 = v cols)
    const int rg = lane >> 4;          // 0,1
    const int cg = lane & 15;          // 0..15
    const int gg = rb * 2 + rg;        // row group 0..3 (10 rows each)
    const int col = cb * 32 + cg * 2;  // two cols: col, col+1
    const bool is_f = (cb < 2);

    // staging identity: lane -> (sgg, sks, sjh)
    const int sgg = lane >> 3;         // 0..3
    const int sks = (lane >> 1) & 3;   // 0..3
    const int sjh = lane & 1;          // 0..1

    // ---- stage W, bc, fq ----
    {
        const float4* gw = reinterpret_cast<const float4*>(g_Wc + h * 16384);
        float4* ws4 = reinterpret_cast<float4*>(W_s);
#pragma unroll
        for (int i = 0; i < 16; ++i) ws4[tid + 256 * i] = gw[tid + 256 * i];
    }
    if (tid < 128) bc_s[tid] = g_bc[h * 128 + tid];
    if (tid < 64)  fq_s[tid] = g_fq[b * 256 + h * 64 + tid];

    const float t1a = tau1[h], t1b = tau1[4 + h];
    const float cb1v = tau2[h], cb2v = tau2[4 + h], cb3v = tau2[8 + h];

    const float bcv0 = bc_s[col] /*note: bc_s staged below sync? stage from global instead*/ ;
    // (bc_s may not be visible yet; load bc directly from global to be safe)
    const float bc0 = g_bc[h * 128 + col];
    const float bc1 = g_bc[h * 128 + col + 1];
    (void)bcv0;
    float fqv0 = 0.f, fqv1 = 0.f;
    if (is_f) { fqv0 = g_fq[b * 256 + h * 64 + col]; fqv1 = g_fq[b * 256 + h * 64 + col + 1]; }

    const float4* fact4 = reinterpret_cast<const float4*>(fact + (long)b * 200 * 128);

    // ---- preload + stage tile 0 ----
    float4 nr[5];
#pragma unroll
    for (int jj = 0; jj < 5; ++jj) {
        int j5 = jj + sks; if (j5 >= 5) j5 -= 5;
        int j = 5 * sjh + j5;
        nr[jj] = fact4[(10 * sgg + j) * 32 + 4 * w + sks];
    }
#pragma unroll
    for (int jj = 0; jj < 5; ++jj) {
        int j5 = jj + sks; if (j5 >= 5) j5 -= 5;
        int j = 5 * sjh + j5;
        float* d = fdT + 12 * sgg + j;
        int kb = 16 * w + 4 * sks;
        d[(kb + 0) * 48] = nr[jj].x;
        d[(kb + 1) * 48] = nr[jj].y;
        d[(kb + 2) * 48] = nr[jj].z;
        d[(kb + 3) * 48] = nr[jj].w;
    }
    __syncthreads();

    // online-softmax state (v-warps); lane owns 2 v-cols, rows of its gg-group
    float m_run = -FLT_MAX, S_run = 0.f;
    float o0 = 0.f, o1 = 0.f, p0 = 0.f, p1 = 0.f;

#pragma unroll 1
    for (int t = 0; t < 5; ++t) {
        // prefetch next tile into regs (overlaps mainloop)
        if (t < 4) {
            const int tb1 = (t + 1) * 40;
#pragma unroll
            for (int jj = 0; jj < 5; ++jj) {
                int j5 = jj + sks; if (j5 >= 5) j5 -= 5;
                int j = 5 * sjh + j5;
                nr[jj] = fact4[(tb1 + 10 * sgg + j) * 32 + 4 * w + sks];
            }
        }

        // ---- mainloop: 5 row-pairs x 2 cols per lane ----
        unsigned long long acc[5][2];
#pragma unroll
        for (int p = 0; p < 5; ++p) { acc[p][0] = 0ull; acc[p][1] = 0ull; }
        {
            const float* ap = fdT + 12 * gg;
            const float* wp = W_s + col;
#pragma unroll 8
            for (int k = 0; k < 128; ++k) {
                ulonglong2 a01 = *reinterpret_cast<const ulonglong2*>(ap);      // pairs j0-1, j2-3
                ulonglong2 a23 = *reinterpret_cast<const ulonglong2*>(ap + 4);  // pairs j4-5, j6-7
                unsigned long long a4 = *reinterpret_cast<const unsigned long long*>(ap + 8); // j8-9
                float2 wv = *reinterpret_cast<const float2*>(wp);
                unsigned long long w0 = dup2(wv.x);
                unsigned long long w1 = dup2(wv.y);
                ffma2(acc[0][0], a01.x, w0); ffma2(acc[0][1], a01.x, w1);
                ffma2(acc[1][0], a01.y, w0); ffma2(acc[1][1], a01.y, w1);
                ffma2(acc[2][0], a23.x, w0); ffma2(acc[2][1], a23.x, w1);
                ffma2(acc[3][0], a23.y, w0); ffma2(acc[3][1], a23.y, w1);
                ffma2(acc[4][0], a4,    w0); ffma2(acc[4][1], a4,    w1);
                ap += 48; wp += 128;
            }
        }

        // ---- epilogue part 1 ----
        float sv[10][2];   // v-warps: silu'd values; f-warps: reuse as pdot staging
        if (is_f) {
            float pdsum[10];
#pragma unroll
            for (int p = 0; p < 5; ++p) {
                float2 c0 = unpk(acc[p][0]);   // col0: rows 2p, 2p+1
                float2 c1 = unpk(acc[p][1]);   // col1
                float s00 = silu_f(c0.x + bc0), s01 = silu_f(c1.x + bc1);
                float s10 = silu_f(c0.y + bc0), s11 = silu_f(c1.y + bc1);
                pdsum[2 * p]     = s00 * fqv0 + s01 * fqv1;
                pdsum[2 * p + 1] = s10 * fqv0 + s11 * fqv1;
            }
#pragma unroll
            for (int j = 0; j < 10; ++j) {
#pragma unroll
                for (int off = 8; off > 0; off >>= 1)
                    pdsum[j] += __shfl_xor_sync(0xffffffffu, pdsum[j], off);
            }
            float mine = pdsum[0];
#pragma unroll
            for (int j = 1; j < 10; ++j)
                if (cg == j) mine = pdsum[j];
            float* pdp = (cb == 0) ? pd0 : pd1;
            if (cg < 10) pdp[10 * gg + cg] = mine;
        } else {
#pragma unroll
            for (int p = 0; p < 5; ++p) {
                float2 c0 = unpk(acc[p][0]);
                float2 c1 = unpk(acc[p][1]);
                sv[2 * p][0]     = silu_f(c0.x + bc0);
                sv[2 * p][1]     = silu_f(c1.x + bc1);
                sv[2 * p + 1][0] = silu_f(c0.y + bc0);
                sv[2 * p + 1][1] = silu_f(c1.y + bc1);
            }
        }
        __syncthreads();   // pd ready; fdT(t) fully consumed by all warps

        // logits for this tile
        if (tid < 40) {
            int l = t * 40 + tid;
            float dd = pd0[tid] + pd1[tid];
            float mk = (float)mask[b * 200 + l];
            dd += (-1e9f) * (1.f - mk);      // mask BEFORE cosine mixing (matches ref)
            float bias = mm[b * 200 + l] / t1a + mm[204800 + b * 200 + l] / t1b;
            lg_s[tid] = cb1v * dd + cb2v * bias + cb3v * dd * bias;
        }
        // stage next tile into fdT
        if (t < 4) {
#pragma unroll
            for (int jj = 0; jj < 5; ++jj) {
                int j5 = jj + sks; if (j5 >= 5) j5 -= 5;
                int j = 5 * sjh + j5;
                float* d = fdT + 12 * sgg + j;
                int kb = 16 * w + 4 * sks;
                d[(kb + 0) * 48] = nr[jj].x;
                d[(kb + 1) * 48] = nr[jj].y;
                d[(kb + 2) * 48] = nr[jj].z;
                d[(kb + 3) * 48] = nr[jj].w;
            }
        }
        __syncthreads();   // lg_s + fdT(t+1) visible

        // v-warps: online softmax accumulate
        if (!is_f) {
#pragma unroll
            for (int j = 0; j < 10; ++j) {
                float lgv = lg_s[10 * gg + j];
                float mn = fmaxf(m_run, lgv);
                float sc = __expf(m_run - mn);   // 0 when m_run = -FLT_MAX
                float e  = __expf(lgv - mn);
                S_run = S_run * sc + e;
                o0 = o0 * sc + e * sv[j][0];
                o1 = o1 * sc + e * sv[j][1];
                p0 += sv[j][0];
                p1 += sv[j][1];
                m_run = mn;
            }
        }
    }

    // ---- merge 4 gg-groups ----
    if (!is_f) {
        int cv = col - 64;   // 0..62 even
        mo[gg * 64 + cv]     = o0;
        mo[gg * 64 + cv + 1] = o1;
        mp[gg * 64 + cv]     = p0;
        mp[gg * 64 + cv + 1] = p1;
        if (cg == 0 && cb == 2) { mSs[gg] = m_run; mSs[4 + gg] = S_run; }
    }
    __syncthreads();

    if (tid < 64) {
        float M = fmaxf(fmaxf(mSs[0], mSs[1]), fmaxf(mSs[2], mSs[3]));
        float e0 = __expf(mSs[0] - M), e1 = __expf(mSs[1] - M);
        float e2 = __expf(mSs[2] - M), e3 = __expf(mSs[3] - M);
        float S = mSs[4] * e0 + mSs[5] * e1 + mSs[6] * e2 + mSs[7] * e3;
        float o = mo[tid] * e0 + mo[64 + tid] * e1 + mo[128 + tid] * e2 + mo[192 + tid] * e3;
        float p = mp[tid] + mp[64 + tid] + mp[128 + tid] + mp[192 + tid];
        out[b * 256 + h * 64 + tid] = o / S + 1e-7f * p;
    }
}

extern "C" void kernel_launch(void* const* d_in, const int* in_sizes, int n_in,
                              void* d_out, int out_size) {
    const float* query = (const float*)d_in[0];
    const float* fact  = (const float*)d_in[1];
    const int*   mask  = (const int*)  d_in[2];
    const float* mm    = (const float*)d_in[3];
    const float* Wq1   = (const float*)d_in[4];
    const float* bq1   = (const float*)d_in[5];
    const float* Wq2   = (const float*)d_in[6];
    const float* bq2   = (const float*)d_in[7];
    const float* Wf1   = (const float*)d_in[8];
    const float* bf1   = (const float*)d_in[9];
    const float* Wf2   = (const float*)d_in[10];
    const float* bf2   = (const float*)d_in[11];
    const float* Wv1   = (const float*)d_in[12];
    const float* bv1   = (const float*)d_in[13];
    const float* Wv2   = (const float*)d_in[14];
    const float* bv2   = (const float*)d_in[15];
    const float* tau1  = (const float*)d_in[16];
    const float* tau2  = (const float*)d_in[17];
    float* out = (float*)d_out;

    cudaFuncSetAttribute(mha_main_kernel, cudaFuncAttributeMaxDynamicSharedMemorySize, SMEM_BYTES);

    collapse_q_kernel<<<512, 256>>>(Wq1, bq1, Wq2, bq2);
    collapse_fv_kernel<<<256, 256>>>(Wf1, bf1, Wf2, bf2, Wv1, bv1, Wv2, bv2);
    fq_kernel<<<128, 256>>>(query);
    mha_main_kernel<<<BB * HH, 256, SMEM_BYTES>>>(fact, mask, mm, tau1, tau2, out);
}

// round 5
// speedup vs baseline: 1.4940x; 1.0068x over previous
#include <cuda_runtime.h>
#include <float.h>

#define HH 4
#define BB 1024
#define LL 200
#define DQv 512
#define DFv 128
#define DD1 128
#define DD2 64

// Collapsed weights + precomputed fq (static device scratch — allowed)
__device__ float g_Wq[HH * DQv * DD2];   // [h][k][c]
__device__ float g_bq[HH * DD2];
__device__ float g_Wc[HH * DFv * 128];   // [h][k][c]  c<64: f-path, c>=64: v-path
__device__ float g_bc[HH * 128];
__device__ float g_fq[BB * HH * DD2];    // [b][h][c] silu(query@Wq_eff+bq_eff)

// ---------------- packed f32x2 helpers ----------------
__device__ __forceinline__ void ffma2(unsigned long long& d, unsigned long long a, unsigned long long b) {
    asm("fma.rn.f32x2 %0, %1, %2, %0;" : "+l"(d) : "l"(a), "l"(b));
}
__device__ __forceinline__ unsigned long long dup2(float x) {
    unsigned long long r;
    unsigned int u = __float_as_uint(x);
    asm("mov.b64 %0, {%1, %1};" : "=l"(r) : "r"(u));
    return r;
}
__device__ __forceinline__ float2 unpk(unsigned long long v) {
    unsigned int lo, hi;
    asm("mov.b64 {%0, %1}, %2;" : "=r"(lo), "=r"(hi) : "l"(v));
    return make_float2(__uint_as_float(lo), __uint_as_float(hi));
}
__device__ __forceinline__ float silu_f(float x) {
    return x / (1.f + __expf(-x));
}

// ---------------- weight collapse kernels ----------------
__global__ void collapse_q_kernel(const float* __restrict__ Wq1, const float* __restrict__ bq1,
                                  const float* __restrict__ Wq2, const float* __restrict__ bq2) {
    int idx = blockIdx.x * 256 + threadIdx.x;      // < 4*512*64 = 131072
    int c = idx & 63;
    int k = (idx >> 6) & 511;
    int h = idx >> 15;
    const float* a  = Wq1 + (h * DQv + k) * DD1;
    const float* w2 = Wq2 + h * DD1 * DD2 + c;
    float acc = 0.f;
#pragma unroll 8
    for (int j = 0; j < DD1; ++j) acc += a[j] * w2[j * DD2];
    g_Wq[idx] = acc;
    if (k == 0) {
        float bb = bq2[h * DD2 + c];
        const float* b1p = bq1 + h * DD1;
#pragma unroll 8
        for (int j = 0; j < DD1; ++j) bb += b1p[j] * w2[j * DD2];
        g_bq[h * DD2 + c] = bb;
    }
}

__global__ void collapse_fv_kernel(const float* __restrict__ Wf1, const float* __restrict__ bf1,
                                   const float* __restrict__ Wf2, const float* __restrict__ bf2,
                                   const float* __restrict__ Wv1, const float* __restrict__ bv1,
                                   const float* __restrict__ Wv2, const float* __restrict__ bv2) {
    int idx = blockIdx.x * 256 + threadIdx.x;      // < 4*128*128 = 65536
    int c = idx & 127;
    int k = (idx >> 7) & 127;
    int h = idx >> 14;
    const float *W1, *W2, *B1, *B2;
    int cc;
    if (c < 64) { W1 = Wf1; W2 = Wf2; B1 = bf1; B2 = bf2; cc = c; }
    else        { W1 = Wv1; W2 = Wv2; B1 = bv1; B2 = bv2; cc = c - 64; }
    const float* a  = W1 + (h * DFv + k) * DD1;
    const float* w2 = W2 + h * DD1 * DD2 + cc;
    float acc = 0.f;
#pragma unroll 8
    for (int j = 0; j < DD1; ++j) acc += a[j] * w2[j * DD2];
    g_Wc[idx] = acc;
    if (k == 0) {
        float bb = B2[h * DD2 + cc];
        const float* b1p = B1 + h * DD1;
#pragma unroll 8
        for (int j = 0; j < DD1; ++j) bb += b1p[j] * w2[j * DD2];
        g_bc[h * 128 + c] = bb;
    }
}

// ---------------- fq kernel ----------------
__global__ __launch_bounds__(256) void fq_kernel(const float* __restrict__ query) {
    __shared__ float qs[32 * 68];
    __shared__ float ws[64 * 64];
    const int tid = threadIdx.x;
    const int h  = blockIdx.x & 3;
    const int bg = blockIdx.x >> 2;
    const int bl = tid >> 3;
    const int cg = tid & 7;

    float acc[8];
#pragma unroll
    for (int j = 0; j < 8; ++j) acc[j] = 0.f;

    for (int kc = 0; kc < 8; ++kc) {
        __syncthreads();
#pragma unroll
        for (int it = 0; it < 8; ++it) {
            int idx = tid + it * 256;
            int bb = idx >> 6, kk = idx & 63;
            qs[bb * 68 + kk] = query[(bg * 32 + bb) * DQv + kc * 64 + kk];
        }
#pragma unroll
        for (int it = 0; it < 16; ++it) {
            int idx = tid + it * 256;
            int kk = idx >> 6, cc = idx & 63;
            ws[kk * 64 + cc] = g_Wq[(h * DQv + kc * 64 + kk) * DD2 + cc];
        }
        __syncthreads();
#pragma unroll 4
        for (int k = 0; k < 64; ++k) {
            float qv = qs[bl * 68 + k];
            float4 w01 = *reinterpret_cast<const float4*>(ws + k * 64 + cg * 8);
            float4 w23 = *reinterpret_cast<const float4*>(ws + k * 64 + cg * 8 + 4);
            acc[0] += qv * w01.x; acc[1] += qv * w01.y;
            acc[2] += qv * w01.z; acc[3] += qv * w01.w;
            acc[4] += qv * w23.x; acc[5] += qv * w23.y;
            acc[6] += qv * w23.z; acc[7] += qv * w23.w;
        }
    }
    int bglob = bg * 32 + bl;
#pragma unroll
    for (int j = 0; j < 8; ++j) {
        int c = cg * 8 + j;
        float z = acc[j] + g_bq[h * DD2 + c];
        g_fq[bglob * 256 + h * 64 + c] = silu_f(z);
    }
}

// ---------------- fused main kernel: one block per (b,h), 2 CTAs/SM ----------------
// 8 warps = 2 rb (20 rows each) x 4 cb (32 cols each). Lane: rg = lane>>4 (10 rows,
// 5 row-pairs), cg = lane&15 (2 cols). Row-pair-packed f32x2 accumulation:
// acc[p][c] = { out[2p][c], out[2p+1][c] }, multiplier pair loaded directly from
// transposed fact tile fdT[k][12*gg + j] (gg = 2rb+rg, j=0..9, pad to 12).
//
// smem floats: W 16384 | fdT 6144 | lg 48 | pd0 48 | pd1 48 | fq 64 | bc 128
//              | mo 256 | mp 256 | mS 16   -> 23392 floats = 93568 B -> 2 CTAs/SM
#define OFF_FDT  16384
#define OFF_LG   (OFF_FDT + 6144)
#define OFF_PD0  (OFF_LG + 48)
#define OFF_PD1  (OFF_PD0 + 48)
#define OFF_FQ   (OFF_PD1 + 48)
#define OFF_BC   (OFF_FQ + 64)
#define OFF_MO   (OFF_BC + 128)
#define OFF_MP   (OFF_MO + 256)
#define OFF_MS   (OFF_MP + 256)
#define SMEM_FLOATS (OFF_MS + 16)
#define SMEM_BYTES  (SMEM_FLOATS * 4)

__global__ __launch_bounds__(256, 2) void mha_main_kernel(
    const float* __restrict__ fact,
    const int* __restrict__ mask, const float* __restrict__ mm,
    const float* __restrict__ tau1, const float* __restrict__ tau2,
    float* __restrict__ out)
{
    extern __shared__ float sm[];
    float* W_s  = sm;              // [128 k][128 c]
    float* fdT  = sm + OFF_FDT;    // [128 k][48]  (4 gg-groups of 12: rows j=0..9 + pad)
    float* lg_s = sm + OFF_LG;     // [40]
    float* pd0  = sm + OFF_PD0;    // [40]
    float* pd1  = sm + OFF_PD1;    // [40]
    float* fq_s = sm + OFF_FQ;     // [64]
    float* bc_s = sm + OFF_BC;     // [128]
    float* mo   = sm + OFF_MO;     // [4][64]
    float* mp   = sm + OFF_MP;     // [4][64]
    float* mSs  = sm + OFF_MS;     // [8]

    const int tid = threadIdx.x;
    const int b = blockIdx.x >> 2;
    const int h = blockIdx.x & 3;
    const int w    = tid >> 5;
    const int lane = tid & 31;
    const int rb = w >> 2;             // 0,1
    const int cb = w & 3;              // 0..3 (0,1 = f cols; 2,3 = v cols)
    const int rg = lane >> 4;          // 0,1
    const int cg = lane & 15;          // 0..15
    const int gg = rb * 2 + rg;        // row group 0..3 (10 rows each)
    const int col = cb * 32 + cg * 2;  // two cols: col, col+1
    const bool is_f = (cb < 2);

    // staging identity: lane -> (sgg, sks, sjh)
    const int sgg = lane >> 3;         // 0..3
    const int sks = (lane >> 1) & 3;   // 0..3
    const int sjh = lane & 1;          // 0..1

    // ---- stage W, bc, fq ----
    {
        const float4* gw = reinterpret_cast<const float4*>(g_Wc + h * 16384);
        float4* ws4 = reinterpret_cast<float4*>(W_s);
#pragma unroll
        for (int i = 0; i < 16; ++i) ws4[tid + 256 * i] = gw[tid + 256 * i];
    }
    if (tid < 128) bc_s[tid] = g_bc[h * 128 + tid];
    if (tid < 64)  fq_s[tid] = g_fq[b * 256 + h * 64 + tid];

    const float t1a = tau1[h], t1b = tau1[4 + h];
    const float cb1v = tau2[h], cb2v = tau2[4 + h], cb3v = tau2[8 + h];

    const float bcv0 = bc_s[col] /*note: bc_s staged below sync? stage from global instead*/ ;
    // (bc_s may not be visible yet; load bc directly from global to be safe)
    const float bc0 = g_bc[h * 128 + col];
    const float bc1 = g_bc[h * 128 + col + 1];
    (void)bcv0;
    float fqv0 = 0.f, fqv1 = 0.f;
    if (is_f) { fqv0 = g_fq[b * 256 + h * 64 + col]; fqv1 = g_fq[b * 256 + h * 64 + col + 1]; }

    const float4* fact4 = reinterpret_cast<const float4*>(fact + (long)b * 200 * 128);

    // ---- preload + stage tile 0 ----
    float4 nr[5];
#pragma unroll
    for (int jj = 0; jj < 5; ++jj) {
        int j5 = jj + sks; if (j5 >= 5) j5 -= 5;
        int j = 5 * sjh + j5;
        nr[jj] = fact4[(10 * sgg + j) * 32 + 4 * w + sks];
    }
#pragma unroll
    for (int jj = 0; jj < 5; ++jj) {
        int j5 = jj + sks; if (j5 >= 5) j5 -= 5;
        int j = 5 * sjh + j5;
        float* d = fdT + 12 * sgg + j;
        int kb = 16 * w + 4 * sks;
        d[(kb + 0) * 48] = nr[jj].x;
        d[(kb + 1) * 48] = nr[jj].y;
        d[(kb + 2) * 48] = nr[jj].z;
        d[(kb + 3) * 48] = nr[jj].w;
    }
    __syncthreads();

    // online-softmax state (v-warps); lane owns 2 v-cols, rows of its gg-group
    float m_run = -FLT_MAX, S_run = 0.f;
    float o0 = 0.f, o1 = 0.f, p0 = 0.f, p1 = 0.f;

#pragma unroll 1
    for (int t = 0; t < 5; ++t) {
        // prefetch next tile into regs (overlaps mainloop)
        if (t < 4) {
            const int tb1 = (t + 1) * 40;
#pragma unroll
            for (int jj = 0; jj < 5; ++jj) {
                int j5 = jj + sks; if (j5 >= 5) j5 -= 5;
                int j = 5 * sjh + j5;
                nr[jj] = fact4[(tb1 + 10 * sgg + j) * 32 + 4 * w + sks];
            }
        }

        // ---- mainloop: 5 row-pairs x 2 cols per lane ----
        unsigned long long acc[5][2];
#pragma unroll
        for (int p = 0; p < 5; ++p) { acc[p][0] = 0ull; acc[p][1] = 0ull; }
        {
            const float* ap = fdT + 12 * gg;
            const float* wp = W_s + col;
#pragma unroll 8
            for (int k = 0; k < 128; ++k) {
                ulonglong2 a01 = *reinterpret_cast<const ulonglong2*>(ap);      // pairs j0-1, j2-3
                ulonglong2 a23 = *reinterpret_cast<const ulonglong2*>(ap + 4);  // pairs j4-5, j6-7
                unsigned long long a4 = *reinterpret_cast<const unsigned long long*>(ap + 8); // j8-9
                float2 wv = *reinterpret_cast<const float2*>(wp);
                unsigned long long w0 = dup2(wv.x);
                unsigned long long w1 = dup2(wv.y);
                ffma2(acc[0][0], a01.x, w0); ffma2(acc[0][1], a01.x, w1);
                ffma2(acc[1][0], a01.y, w0); ffma2(acc[1][1], a01.y, w1);
                ffma2(acc[2][0], a23.x, w0); ffma2(acc[2][1], a23.x, w1);
                ffma2(acc[3][0], a23.y, w0); ffma2(acc[3][1], a23.y, w1);
                ffma2(acc[4][0], a4,    w0); ffma2(acc[4][1], a4,    w1);
                ap += 48; wp += 128;
            }
        }

        // ---- epilogue part 1 ----
        float sv[10][2];   // v-warps: silu'd values; f-warps: reuse as pdot staging
        if (is_f) {
            float pdsum[10];
#pragma unroll
            for (int p = 0; p < 5; ++p) {
                float2 c0 = unpk(acc[p][0]);   // col0: rows 2p, 2p+1
                float2 c1 = unpk(acc[p][1]);   // col1
                float s00 = silu_f(c0.x + bc0), s01 = silu_f(c1.x + bc1);
                float s10 = silu_f(c0.y + bc0), s11 = silu_f(c1.y + bc1);
                pdsum[2 * p]     = s00 * fqv0 + s01 * fqv1;
                pdsum[2 * p + 1] = s10 * fqv0 + s11 * fqv1;
            }
#pragma unroll
            for (int j = 0; j < 10; ++j) {
#pragma unroll
                for (int off = 8; off > 0; off >>= 1)
                    pdsum[j] += __shfl_xor_sync(0xffffffffu, pdsum[j], off);
            }
            float mine = pdsum[0];
#pragma unroll
            for (int j = 1; j < 10; ++j)
                if (cg == j) mine = pdsum[j];
            float* pdp = (cb == 0) ? pd0 : pd1;
            if (cg < 10) pdp[10 * gg + cg] = mine;
        } else {
#pragma unroll
            for (int p = 0; p < 5; ++p) {
                float2 c0 = unpk(acc[p][0]);
                float2 c1 = unpk(acc[p][1]);
                sv[2 * p][0]     = silu_f(c0.x + bc0);
                sv[2 * p][1]     = silu_f(c1.x + bc1);
                sv[2 * p + 1][0] = silu_f(c0.y + bc0);
                sv[2 * p + 1][1] = silu_f(c1.y + bc1);
            }
        }
        __syncthreads();   // pd ready; fdT(t) fully consumed by all warps

        // logits for this tile
        if (tid < 40) {
            int l = t * 40 + tid;
            float dd = pd0[tid] + pd1[tid];
            float mk = (float)mask[b * 200 + l];
            dd += (-1e9f) * (1.f - mk);      // mask BEFORE cosine mixing (matches ref)
            float bias = mm[b * 200 + l] / t1a + mm[204800 + b * 200 + l] / t1b;
            lg_s[tid] = cb1v * dd + cb2v * bias + cb3v * dd * bias;
        }
        // stage next tile into fdT
        if (t < 4) {
#pragma unroll
            for (int jj = 0; jj < 5; ++jj) {
                int j5 = jj + sks; if (j5 >= 5) j5 -= 5;
                int j = 5 * sjh + j5;
                float* d = fdT + 12 * sgg + j;
                int kb = 16 * w + 4 * sks;
                d[(kb + 0) * 48] = nr[jj].x;
                d[(kb + 1) * 48] = nr[jj].y;
                d[(kb + 2) * 48] = nr[jj].z;
                d[(kb + 3) * 48] = nr[jj].w;
            }
        }
        __syncthreads();   // lg_s + fdT(t+1) visible

        // v-warps: online softmax accumulate
        if (!is_f) {
#pragma unroll
            for (int j = 0; j < 10; ++j) {
                float lgv = lg_s[10 * gg + j];
                float mn = fmaxf(m_run, lgv);
                float sc = __expf(m_run - mn);   // 0 when m_run = -FLT_MAX
                float e  = __expf(lgv - mn);
                S_run = S_run * sc + e;
                o0 = o0 * sc + e * sv[j][0];
                o1 = o1 * sc + e * sv[j][1];
                p0 += sv[j][0];
                p1 += sv[j][1];
                m_run = mn;
            }
        }
    }

    // ---- merge 4 gg-groups ----
    if (!is_f) {
        int cv = col - 64;   // 0..62 even
        mo[gg * 64 + cv]     = o0;
        mo[gg * 64 + cv + 1] = o1;
        mp[gg * 64 + cv]     = p0;
        mp[gg * 64 + cv + 1] = p1;
        if (cg == 0 && cb == 2) { mSs[gg] = m_run; mSs[4 + gg] = S_run; }
    }
    __syncthreads();

    if (tid < 64) {
        float M = fmaxf(fmaxf(mSs[0], mSs[1]), fmaxf(mSs[2], mSs[3]));
        float e0 = __expf(mSs[0] - M), e1 = __expf(mSs[1] - M);
        float e2 = __expf(mSs[2] - M), e3 = __expf(mSs[3] - M);
        float S = mSs[4] * e0 + mSs[5] * e1 + mSs[6] * e2 + mSs[7] * e3;
        float o = mo[tid] * e0 + mo[64 + tid] * e1 + mo[128 + tid] * e2 + mo[192 + tid] * e3;
        float p = mp[tid] + mp[64 + tid] + mp[128 + tid] + mp[192 + tid];
        out[b * 256 + h * 64 + tid] = o / S + 1e-7f * p;
    }
}

extern "C" void kernel_launch(void* const* d_in, const int* in_sizes, int n_in,
                              void* d_out, int out_size) {
    const float* query = (const float*)d_in[0];
    const float* fact  = (const float*)d_in[1];
    const int*   mask  = (const int*)  d_in[2];
    const float* mm    = (const float*)d_in[3];
    const float* Wq1   = (const float*)d_in[4];
    const float* bq1   = (const float*)d_in[5];
    const float* Wq2   = (const float*)d_in[6];
    const float* bq2   = (const float*)d_in[7];
    const float* Wf1   = (const float*)d_in[8];
    const float* bf1   = (const float*)d_in[9];
    const float* Wf2   = (const float*)d_in[10];
    const float* bf2   = (const float*)d_in[11];
    const float* Wv1   = (const float*)d_in[12];
    const float* bv1   = (const float*)d_in[13];
    const float* Wv2   = (const float*)d_in[14];
    const float* bv2   = (const float*)d_in[15];
    const float* tau1  = (const float*)d_in[16];
    const float* tau2  = (const float*)d_in[17];
    float* out = (float*)d_out;

    cudaFuncSetAttribute(mha_main_kernel, cudaFuncAttributeMaxDynamicSharedMemorySize, SMEM_BYTES);

    collapse_q_kernel<<<512, 256>>>(Wq1, bq1, Wq2, bq2);
    collapse_fv_kernel<<<256, 256>>>(Wf1, bf1, Wf2, bf2, Wv1, bv1, Wv2, bv2);
    fq_kernel<<<128, 256>>>(query);
    mha_main_kernel<<<BB * HH, 256, SMEM_BYTES>>>(fact, mask, mm, tau1, tau2, out);
}